// round 8
// baseline (speedup 1.0000x reference)
#include <cuda_runtime.h>
#include <cuda_bf16.h>
#include <cstdint>
#include <cstddef>

#define DEVINL __device__ __forceinline__

#define BB 8192
#define LL 2048
#define NFLOW 8

// GEMM tiling: CTA 128(M) x 256(N), 512 threads, 16 warps as 2(M) x 8(N) -> warp 64x32
#define BM 128
#define BN 256
#define BK 32
#define NKI (LL / BK)              // 64 k-chunks
#define NSTAGE 3

// smem rows padded to 80B (64B data + 16B pad) -> conflict-free ldmatrix
#define ROWB 80
#define OFF_AH 0
#define OFF_AL (128 * ROWB)                 // 10240
#define OFF_BH (2 * 128 * ROWB)             // 20480
#define OFF_BL (OFF_BH + 256 * ROWB)        // 40960
#define STAGE_BYTES (OFF_BL + 256 * ROWB)   // 61440
#define SMEM_TOTAL (NSTAGE * STAGE_BYTES)   // 184320

// ---------------- scratch ----------------
__device__ __nv_bfloat16 g_VhiA[(size_t)BB * LL];
__device__ __nv_bfloat16 g_VloA[(size_t)BB * LL];
__device__ __nv_bfloat16 g_VhiB[(size_t)BB * LL];
__device__ __nv_bfloat16 g_VloB[(size_t)BB * LL];
__device__ __nv_bfloat16 g_Whi[(size_t)NFLOW * LL * LL];
__device__ __nv_bfloat16 g_Wlo[(size_t)NFLOW * LL * LL];

// ---------------- PTX helpers ----------------
DEVINL uint32_t smem_u32(const void* p) {
    uint32_t a;
    asm("{ .reg .u64 t; cvta.to.shared.u64 t, %1; cvt.u32.u64 %0, t; }" : "=r"(a) : "l"(p));
    return a;
}
DEVINL void cp_async16(uint32_t saddr, const void* gaddr) {
    asm volatile("cp.async.cg.shared.global [%0], [%1], 16;" :: "r"(saddr), "l"(gaddr) : "memory");
}
DEVINL void cp_commit() { asm volatile("cp.async.commit_group;" ::: "memory"); }
DEVINL void cp_wait1() { asm volatile("cp.async.wait_group 1;" ::: "memory"); }
DEVINL void cp_wait0() { asm volatile("cp.async.wait_group 0;" ::: "memory"); }

DEVINL void ldsm_x4(uint32_t& r0, uint32_t& r1, uint32_t& r2, uint32_t& r3, uint32_t saddr) {
    asm volatile("ldmatrix.sync.aligned.m8n8.x4.shared.b16 {%0,%1,%2,%3}, [%4];"
                 : "=r"(r0), "=r"(r1), "=r"(r2), "=r"(r3) : "r"(saddr));
}
DEVINL void mma_bf16(float* d, const uint32_t* a, const uint32_t* b) {
    asm volatile(
        "mma.sync.aligned.m16n8k16.row.col.f32.bf16.bf16.f32 "
        "{%0,%1,%2,%3}, {%4,%5,%6,%7}, {%8,%9}, {%0,%1,%2,%3};"
        : "+f"(d[0]), "+f"(d[1]), "+f"(d[2]), "+f"(d[3])
        : "r"(a[0]), "r"(a[1]), "r"(a[2]), "r"(a[3]), "r"(b[0]), "r"(b[1]));
}
DEVINL uint32_t pack_bf2(float a, float b) {
    __nv_bfloat162 t; t.x = __float2bfloat16(a); t.y = __float2bfloat16(b);
    return *reinterpret_cast<uint32_t*>(&t);
}
DEVINL void split2(float a, float b, uint32_t& hi, uint32_t& lo) {
    float ha = __bfloat162float(__float2bfloat16(a));
    float hb = __bfloat162float(__float2bfloat16(b));
    hi = pack_bf2(ha, hb);
    lo = pack_bf2(a - ha, b - hb);
}

// ---------------- split: fp32 -> bf16 hi/lo ----------------
__global__ void __launch_bounds__(256) split_kernel(
    const float4* __restrict__ src, uint2* __restrict__ hi, uint2* __restrict__ lo, int n4)
{
    int i = blockIdx.x * 256 + threadIdx.x;
    if (i >= n4) return;
    float4 v = src[i];
    uint2 h, l;
    split2(v.x, v.y, h.x, l.x);
    split2(v.z, v.w, h.y, l.y);
    hi[i] = h; lo[i] = l;
}

// ---------------- fill one pipeline stage ----------------
DEVINL void fill_stage(uint32_t stg,
                       const __nv_bfloat16* __restrict__ Ahi, const __nv_bfloat16* __restrict__ Alo,
                       const __nv_bfloat16* __restrict__ Bhi, const __nv_bfloat16* __restrict__ Blo,
                       size_t arow0, size_t brow0, size_t kb, int tid)
{
    // A: 128 rows x 4 16B-chunks = 512 units, 1 per thread (hi and lo)
    {
        int r = tid >> 2, c = tid & 3;
        uint32_t so = (uint32_t)(r * ROWB + c * 16);
        size_t ga = (arow0 + r) * (size_t)LL + kb + c * 8;
        cp_async16(stg + OFF_AH + so, Ahi + ga);
        cp_async16(stg + OFF_AL + so, Alo + ga);
    }
    // B: 256 rows x 4 = 1024 units, 2 per thread (hi and lo)
    #pragma unroll
    for (int it = 0; it < 2; ++it) {
        int i = tid + it * 512;
        int r = i >> 2, c = i & 3;
        uint32_t so = (uint32_t)(r * ROWB + c * 16);
        size_t gb = (brow0 + r) * (size_t)LL + kb + c * 8;
        cp_async16(stg + OFF_BH + so, Bhi + gb);
        cp_async16(stg + OFF_BL + so, Blo + gb);
    }
    cp_commit();
}

// ---------------- GEMM: v' = A @ W^T + bias, epilogue-split into vhi/vlo ----------------
// bf16 3-product: D = Ah*Bh + Al*Bh + Ah*Bl   (fp32 accumulate)
__global__ void __launch_bounds__(512, 1) gemm_kernel(
    const __nv_bfloat16* __restrict__ Ahi, const __nv_bfloat16* __restrict__ Alo,
    const __nv_bfloat16* __restrict__ Bhi, const __nv_bfloat16* __restrict__ Blo,
    const float* __restrict__ bias,
    __nv_bfloat16* __restrict__ vhi_out, __nv_bfloat16* __restrict__ vlo_out)
{
    extern __shared__ char smem[];
    const uint32_t sb = smem_u32(smem);
    const int tid = threadIdx.x;
    const int lane = tid & 31;
    const int wid = tid >> 5;
    const int warp_m = wid & 1;          // 2 warps along M (64 rows)
    const int warp_n = wid >> 1;         // 8 warps along N (32 cols)
    const size_t arow0 = (size_t)blockIdx.x * BM;
    const size_t brow0 = (size_t)blockIdx.y * BN;

    float acc[4][4][4];
    #pragma unroll
    for (int mi = 0; mi < 4; ++mi)
        #pragma unroll
        for (int ni = 0; ni < 4; ++ni)
            #pragma unroll
            for (int q = 0; q < 4; ++q) acc[mi][ni][q] = 0.0f;

    // ldmatrix addressing (byte offsets within a matrix tile)
    const uint32_t a_row_base = (uint32_t)(warp_m * 64 + (lane & 15));
    const uint32_t a_kb = (uint32_t)((lane >> 4) * 16);
    const uint32_t b_row_base = (uint32_t)(warp_n * 32 + ((lane >> 4) & 1) * 8 + (lane & 7));
    const uint32_t b_kb = (uint32_t)(((lane >> 3) & 1) * 16);

    // ---- prologue: prefetch chunks 0 and 1 into stages 0 and 1 ----
    fill_stage(sb,               Ahi, Alo, Bhi, Blo, arow0, brow0, 0,  tid);
    fill_stage(sb + STAGE_BYTES, Ahi, Alo, Bhi, Blo, arow0, brow0, BK, tid);

    uint32_t stg = sb;          // stage for chunk kc
    uint32_t stg_w = sb + 2 * STAGE_BYTES;   // stage to fill (chunk kc+2)

    for (int kc = 0; kc < NKI; ++kc) {
        // wait for group kc (issued 2 chunks ago); group kc+1 may still be in flight
        cp_wait1();
        __syncthreads();        // stage kc visible to all; reads of stage (kc+2)%3 (chunk kc-1) done

        if (kc + 2 < NKI)
            fill_stage(stg_w, Ahi, Alo, Bhi, Blo, arow0, brow0, (size_t)(kc + 2) * BK, tid);
        else
            cp_commit();        // keep group count in lockstep for wait_group 1

        #pragma unroll
        for (int ks = 0; ks < 2; ++ks) {
            // pass 1: Ah * Bh
            uint32_t Ah[4][4];
            #pragma unroll
            for (int s = 0; s < 4; ++s) {
                uint32_t off = (a_row_base + s * 16) * ROWB + ks * 32 + a_kb;
                ldsm_x4(Ah[s][0], Ah[s][1], Ah[s][2], Ah[s][3], stg + OFF_AH + off);
            }
            uint32_t Bh[4][2];
            #pragma unroll
            for (int p = 0; p < 2; ++p) {
                uint32_t off = (b_row_base + p * 16) * ROWB + ks * 32 + b_kb;
                ldsm_x4(Bh[2*p][0], Bh[2*p][1], Bh[2*p+1][0], Bh[2*p+1][1], stg + OFF_BH + off);
            }
            #pragma unroll
            for (int mi = 0; mi < 4; ++mi)
                #pragma unroll
                for (int ni = 0; ni < 4; ++ni)
                    mma_bf16(acc[mi][ni], Ah[mi], Bh[ni]);

            // pass 2: Al * Bh
            uint32_t Al[4][4];
            #pragma unroll
            for (int s = 0; s < 4; ++s) {
                uint32_t off = (a_row_base + s * 16) * ROWB + ks * 32 + a_kb;
                ldsm_x4(Al[s][0], Al[s][1], Al[s][2], Al[s][3], stg + OFF_AL + off);
            }
            #pragma unroll
            for (int mi = 0; mi < 4; ++mi)
                #pragma unroll
                for (int ni = 0; ni < 4; ++ni)
                    mma_bf16(acc[mi][ni], Al[mi], Bh[ni]);

            // pass 3: Ah * Bl
            uint32_t Bl[4][2];
            #pragma unroll
            for (int p = 0; p < 2; ++p) {
                uint32_t off = (b_row_base + p * 16) * ROWB + ks * 32 + b_kb;
                ldsm_x4(Bl[2*p][0], Bl[2*p][1], Bl[2*p+1][0], Bl[2*p+1][1], stg + OFF_BL + off);
            }
            #pragma unroll
            for (int mi = 0; mi < 4; ++mi)
                #pragma unroll
                for (int ni = 0; ni < 4; ++ni)
                    mma_bf16(acc[mi][ni], Ah[mi], Bl[ni]);
        }

        // rotate stages
        stg_w = stg;
        stg = (stg == sb + 2 * STAGE_BYTES) ? sb : stg + STAGE_BYTES;
    }
    cp_wait0();

    // ---- epilogue: add bias, split fp32 -> bf16 hi/lo, store ----
    const size_t m_base = arow0 + warp_m * 64;
    const size_t n_base = brow0 + warp_n * 32;
    const int tm = lane >> 2, tn = (lane & 3) * 2;
    #pragma unroll
    for (int mi = 0; mi < 4; ++mi) {
        #pragma unroll
        for (int ni = 0; ni < 4; ++ni) {
            size_t col = n_base + ni * 8 + tn;
            float b0 = __ldg(bias + col), b1 = __ldg(bias + col + 1);
            size_t r0 = m_base + mi * 16 + tm;
            float v00 = acc[mi][ni][0] + b0, v01 = acc[mi][ni][1] + b1;
            float v10 = acc[mi][ni][2] + b0, v11 = acc[mi][ni][3] + b1;
            uint32_t h, l;
            split2(v00, v01, h, l);
            *(uint32_t*)(vhi_out + r0 * LL + col) = h;
            *(uint32_t*)(vlo_out + r0 * LL + col) = l;
            split2(v10, v11, h, l);
            *(uint32_t*)(vhi_out + (r0 + 8) * LL + col) = h;
            *(uint32_t*)(vlo_out + (r0 + 8) * LL + col) = l;
        }
    }
}

// ---------------- Householder: z' = z - 2 v (v.z)/(v.v), v = hi+lo ----------------
__global__ void __launch_bounds__(256) hflow_kernel(
    const __nv_bfloat16* __restrict__ vhi, const __nv_bfloat16* __restrict__ vlo,
    const float* __restrict__ zin, float* __restrict__ zout)
{
    __shared__ float red[16];
    __shared__ float s_coef;
    const size_t row = blockIdx.x;
    const int tid = threadIdx.x;
    const uint2* vh4 = (const uint2*)(vhi + row * (size_t)LL);
    const uint2* vl4 = (const uint2*)(vlo + row * (size_t)LL);
    const float4* z4 = (const float4*)(zin + row * (size_t)LL);

    float v[8], z[8];
    #pragma unroll
    for (int h = 0; h < 2; ++h) {
        uint2 hv = vh4[tid + h * 256];
        uint2 lv = vl4[tid + h * 256];
        float4 zz = z4[tid + h * 256];
        __nv_bfloat162 h0 = *(__nv_bfloat162*)&hv.x, h1 = *(__nv_bfloat162*)&hv.y;
        __nv_bfloat162 l0 = *(__nv_bfloat162*)&lv.x, l1 = *(__nv_bfloat162*)&lv.y;
        v[h*4+0] = __bfloat162float(h0.x) + __bfloat162float(l0.x);
        v[h*4+1] = __bfloat162float(h0.y) + __bfloat162float(l0.y);
        v[h*4+2] = __bfloat162float(h1.x) + __bfloat162float(l1.x);
        v[h*4+3] = __bfloat162float(h1.y) + __bfloat162float(l1.y);
        z[h*4+0] = zz.x; z[h*4+1] = zz.y; z[h*4+2] = zz.z; z[h*4+3] = zz.w;
    }

    float vz = 0.f, vv = 0.f;
    #pragma unroll
    for (int i = 0; i < 8; ++i) { vz += v[i] * z[i]; vv += v[i] * v[i]; }
    #pragma unroll
    for (int o = 16; o; o >>= 1) {
        vz += __shfl_xor_sync(0xFFFFFFFFu, vz, o);
        vv += __shfl_xor_sync(0xFFFFFFFFu, vv, o);
    }
    if ((tid & 31) == 0) { red[tid >> 5] = vz; red[8 + (tid >> 5)] = vv; }
    __syncthreads();
    if (tid == 0) {
        float svz = 0.f, svv = 0.f;
        #pragma unroll
        for (int i = 0; i < 8; ++i) { svz += red[i]; svv += red[8 + i]; }
        s_coef = -2.0f * svz / svv;
    }
    __syncthreads();
    const float c = s_coef;

    float4* zo = (float4*)(zout + row * (size_t)LL);
    #pragma unroll
    for (int h = 0; h < 2; ++h) {
        float4 o;
        o.x = z[h*4+0] + c * v[h*4+0];
        o.y = z[h*4+1] + c * v[h*4+1];
        o.z = z[h*4+2] + c * v[h*4+2];
        o.w = z[h*4+3] + c * v[h*4+3];
        zo[tid + h * 256] = o;
    }
}

// ---------------- host ----------------
extern "C" void kernel_launch(void* const* d_in, const int* in_sizes, int n_in,
                              void* d_out, int out_size)
{
    const float* z_in   = (const float*)d_in[0];
    const float* h_last = (const float*)d_in[1];
    const float* W0     = (const float*)d_in[2];
    const float* b0     = (const float*)d_in[3];
    const float* Ws     = (const float*)d_in[4];
    const float* bs     = (const float*)d_in[5];
    float* z_out = (float*)d_out;

    void *pVhiA, *pVloA, *pVhiB, *pVloB, *pWhi, *pWlo;
    cudaGetSymbolAddress(&pVhiA, g_VhiA);
    cudaGetSymbolAddress(&pVloA, g_VloA);
    cudaGetSymbolAddress(&pVhiB, g_VhiB);
    cudaGetSymbolAddress(&pVloB, g_VloB);
    cudaGetSymbolAddress(&pWhi,  g_Whi);
    cudaGetSymbolAddress(&pWlo,  g_Wlo);

    static bool attr_set = false;
    if (!attr_set) {
        cudaFuncSetAttribute(gemm_kernel, cudaFuncAttributeMaxDynamicSharedMemorySize, SMEM_TOTAL);
        attr_set = true;
    }

    const size_t mat = (size_t)LL * LL;
    {
        int n4 = (int)((size_t)BB * LL / 4);
        split_kernel<<<(n4 + 255) / 256, 256>>>((const float4*)h_last, (uint2*)pVhiA, (uint2*)pVloA, n4);
    }
    {
        int n4 = (int)(mat / 4);
        split_kernel<<<(n4 + 255) / 256, 256>>>((const float4*)W0, (uint2*)pWhi, (uint2*)pWlo, n4);
    }
    {
        int n4 = (int)((NFLOW - 1) * mat / 4);
        split_kernel<<<(n4 + 255) / 256, 256>>>((const float4*)Ws,
            (uint2*)((__nv_bfloat16*)pWhi + mat), (uint2*)((__nv_bfloat16*)pWlo + mat), n4);
    }

    dim3 ggrid(BB / BM, LL / BN);   // (64, 8) = 512 CTAs
    void* curHi = pVhiA; void* curLo = pVloA;
    void* nxtHi = pVhiB; void* nxtLo = pVloB;
    for (int j = 0; j < NFLOW; ++j) {
        const __nv_bfloat16* Bh = (const __nv_bfloat16*)pWhi + (size_t)j * mat;
        const __nv_bfloat16* Bl = (const __nv_bfloat16*)pWlo + (size_t)j * mat;
        const float* bias = (j == 0) ? b0 : (bs + (size_t)(j - 1) * LL);
        gemm_kernel<<<ggrid, 512, SMEM_TOTAL>>>(
            (const __nv_bfloat16*)curHi, (const __nv_bfloat16*)curLo, Bh, Bl, bias,
            (__nv_bfloat16*)nxtHi, (__nv_bfloat16*)nxtLo);
        const float* zi = (j == 0) ? z_in : z_out;
        hflow_kernel<<<BB, 256>>>((const __nv_bfloat16*)nxtHi, (const __nv_bfloat16*)nxtLo, zi, z_out);
        void* t;
        t = curHi; curHi = nxtHi; nxtHi = t;
        t = curLo; curLo = nxtLo; nxtLo = t;
    }
}

// round 10
// speedup vs baseline: 1.1423x; 1.1423x over previous
#include <cuda_runtime.h>
#include <cuda_bf16.h>
#include <cstdint>
#include <cstddef>

#define DEVINL __device__ __forceinline__

#define BB 8192
#define LL 2048
#define NFLOW 8

// GEMM tiling (R3 proven config): CTA 128x128xBK32, 256 thr, 2 CTAs/SM, 2-stage
#define BM 128
#define BN 128
#define BK 32
#define NKI (LL / BK)              // 64 k-chunks

// smem rows padded to 80B (64B data + 16B pad) -> conflict-free ldmatrix
#define ROWB 80
#define MAT_BYTES (128 * ROWB)
#define OFF_AH 0
#define OFF_AL (1 * MAT_BYTES)
#define OFF_BH (2 * MAT_BYTES)
#define OFF_BL (3 * MAT_BYTES)
#define STAGE_BYTES (4 * MAT_BYTES)        // 40960
#define SMEM_TOTAL (2 * STAGE_BYTES)       // 81920

// ---------------- scratch ----------------
// v-chain slots: 8 stages of [BB, LL] bf16 hi/lo
__device__ __nv_bfloat16 g_Vhi[(size_t)NFLOW * BB * LL];
__device__ __nv_bfloat16 g_Vlo[(size_t)NFLOW * BB * LL];
__device__ __nv_bfloat16 g_Hhi[(size_t)BB * LL];
__device__ __nv_bfloat16 g_Hlo[(size_t)BB * LL];
__device__ __nv_bfloat16 g_Whi[(size_t)NFLOW * LL * LL];
__device__ __nv_bfloat16 g_Wlo[(size_t)NFLOW * LL * LL];

// ---------------- PTX helpers ----------------
DEVINL uint32_t smem_u32(const void* p) {
    uint32_t a;
    asm("{ .reg .u64 t; cvta.to.shared.u64 t, %1; cvt.u32.u64 %0, t; }" : "=r"(a) : "l"(p));
    return a;
}
DEVINL void cp_async16_cg(uint32_t saddr, const void* gaddr) {
    asm volatile("cp.async.cg.shared.global [%0], [%1], 16;" :: "r"(saddr), "l"(gaddr) : "memory");
}
DEVINL void cp_async16_ca(uint32_t saddr, const void* gaddr) {
    asm volatile("cp.async.ca.shared.global [%0], [%1], 16;" :: "r"(saddr), "l"(gaddr) : "memory");
}
DEVINL void cp_commit() { asm volatile("cp.async.commit_group;" ::: "memory"); }
DEVINL void cp_wait_all() { asm volatile("cp.async.wait_group 0;" ::: "memory"); }

DEVINL void ldsm_x4(uint32_t& r0, uint32_t& r1, uint32_t& r2, uint32_t& r3, uint32_t saddr) {
    asm volatile("ldmatrix.sync.aligned.m8n8.x4.shared.b16 {%0,%1,%2,%3}, [%4];"
                 : "=r"(r0), "=r"(r1), "=r"(r2), "=r"(r3) : "r"(saddr));
}
DEVINL void mma_bf16(float* d, const uint32_t* a, const uint32_t* b) {
    asm volatile(
        "mma.sync.aligned.m16n8k16.row.col.f32.bf16.bf16.f32 "
        "{%0,%1,%2,%3}, {%4,%5,%6,%7}, {%8,%9}, {%0,%1,%2,%3};"
        : "+f"(d[0]), "+f"(d[1]), "+f"(d[2]), "+f"(d[3])
        : "r"(a[0]), "r"(a[1]), "r"(a[2]), "r"(a[3]), "r"(b[0]), "r"(b[1]));
}
DEVINL uint32_t pack_bf2(float a, float b) {
    __nv_bfloat162 t; t.x = __float2bfloat16(a); t.y = __float2bfloat16(b);
    return *reinterpret_cast<uint32_t*>(&t);
}
DEVINL void split2(float a, float b, uint32_t& hi, uint32_t& lo) {
    float ha = __bfloat162float(__float2bfloat16(a));
    float hb = __bfloat162float(__float2bfloat16(b));
    hi = pack_bf2(ha, hb);
    lo = pack_bf2(a - ha, b - hb);
}

// ---------------- split: fp32 -> bf16 hi/lo ----------------
__global__ void __launch_bounds__(256) split_kernel(
    const float4* __restrict__ src, uint2* __restrict__ hi, uint2* __restrict__ lo, int n4)
{
    int i = blockIdx.x * 256 + threadIdx.x;
    if (i >= n4) return;
    float4 v = src[i];
    uint2 h, l;
    split2(v.x, v.y, h.x, l.x);
    split2(v.z, v.w, h.y, l.y);
    hi[i] = h; lo[i] = l;
}

// ---------------- GEMM: v' = A @ W^T + bias, epilogue-split into vhi/vlo ----------------
// bf16 3-product: D = Ah*Bh + Al*Bh + Ah*Bl   (fp32 accumulate)
__global__ void __launch_bounds__(256, 2) gemm_kernel(
    const __nv_bfloat16* __restrict__ Ahi, const __nv_bfloat16* __restrict__ Alo,
    const __nv_bfloat16* __restrict__ Bhi, const __nv_bfloat16* __restrict__ Blo,
    const float* __restrict__ bias,
    __nv_bfloat16* __restrict__ vhi_out, __nv_bfloat16* __restrict__ vlo_out)
{
    extern __shared__ char smem[];
    const uint32_t sb = smem_u32(smem);
    const int tid = threadIdx.x;
    const int lane = tid & 31;
    const int wid = tid >> 5;
    const int warp_m = wid & 3;          // 4 warps along M (32 rows)
    const int warp_n = wid >> 2;         // 2 warps along N (64 cols)
    const size_t arow0 = (size_t)blockIdx.x * BM;
    const size_t brow0 = (size_t)blockIdx.y * BN;

    float acc[2][8][4];
    #pragma unroll
    for (int mi = 0; mi < 2; ++mi)
        #pragma unroll
        for (int ni = 0; ni < 8; ++ni)
            #pragma unroll
            for (int q = 0; q < 4; ++q) acc[mi][ni][q] = 0.0f;

    const uint32_t a_row[2] = {
        (uint32_t)(warp_m * 32 + 0  + (lane & 15)),
        (uint32_t)(warp_m * 32 + 16 + (lane & 15)) };
    const uint32_t a_kb = (uint32_t)((lane >> 4) * 16);
    const uint32_t b_row_base = (uint32_t)(warp_n * 64 + ((lane >> 4) & 1) * 8 + (lane & 7));
    const uint32_t b_kb = (uint32_t)(((lane >> 3) & 1) * 16);

    // ---- prefetch stage 0 ----
    {
        const uint32_t stg = sb;
        #pragma unroll
        for (int it = 0; it < 2; ++it) {
            int i = tid + it * 256;
            int r = i >> 2, c = i & 3;
            uint32_t so = (uint32_t)(r * ROWB + c * 16);
            size_t ga = (arow0 + r) * (size_t)LL + c * 8;
            size_t gb = (brow0 + r) * (size_t)LL + c * 8;
            cp_async16_cg(stg + OFF_AH + so, Ahi + ga);
            cp_async16_cg(stg + OFF_AL + so, Alo + ga);
            cp_async16_ca(stg + OFF_BH + so, Bhi + gb);   // W tiles shared by co-resident CTA -> L1
            cp_async16_ca(stg + OFF_BL + so, Blo + gb);
        }
        cp_commit();
    }

    for (int kc = 0; kc < NKI; ++kc) {
        cp_wait_all();
        __syncthreads();

        if (kc + 1 < NKI) {
            const uint32_t stg = sb + ((kc + 1) & 1) * STAGE_BYTES;
            const size_t kb = (size_t)(kc + 1) * BK;
            #pragma unroll
            for (int it = 0; it < 2; ++it) {
                int i = tid + it * 256;
                int r = i >> 2, c = i & 3;
                uint32_t so = (uint32_t)(r * ROWB + c * 16);
                size_t ga = (arow0 + r) * (size_t)LL + kb + c * 8;
                size_t gb = (brow0 + r) * (size_t)LL + kb + c * 8;
                cp_async16_cg(stg + OFF_AH + so, Ahi + ga);
                cp_async16_cg(stg + OFF_AL + so, Alo + ga);
                cp_async16_ca(stg + OFF_BH + so, Bhi + gb);
                cp_async16_ca(stg + OFF_BL + so, Blo + gb);
            }
            cp_commit();
        }

        const uint32_t stg = sb + (kc & 1) * STAGE_BYTES;

        #pragma unroll
        for (int ks = 0; ks < 2; ++ks) {
            // pass 1: Ah * Bh
            uint32_t Ah[2][4];
            #pragma unroll
            for (int s = 0; s < 2; ++s) {
                uint32_t off = a_row[s] * ROWB + ks * 32 + a_kb;
                ldsm_x4(Ah[s][0], Ah[s][1], Ah[s][2], Ah[s][3], stg + OFF_AH + off);
            }
            uint32_t Bh[8][2];
            #pragma unroll
            for (int p = 0; p < 4; ++p) {
                uint32_t off = (b_row_base + p * 16) * ROWB + ks * 32 + b_kb;
                ldsm_x4(Bh[2*p][0], Bh[2*p][1], Bh[2*p+1][0], Bh[2*p+1][1], stg + OFF_BH + off);
            }
            #pragma unroll
            for (int mi = 0; mi < 2; ++mi)
                #pragma unroll
                for (int ni = 0; ni < 8; ++ni)
                    mma_bf16(acc[mi][ni], Ah[mi], Bh[ni]);

            // pass 2: Al * Bh
            uint32_t Al[2][4];
            #pragma unroll
            for (int s = 0; s < 2; ++s) {
                uint32_t off = a_row[s] * ROWB + ks * 32 + a_kb;
                ldsm_x4(Al[s][0], Al[s][1], Al[s][2], Al[s][3], stg + OFF_AL + off);
            }
            #pragma unroll
            for (int mi = 0; mi < 2; ++mi)
                #pragma unroll
                for (int ni = 0; ni < 8; ++ni)
                    mma_bf16(acc[mi][ni], Al[mi], Bh[ni]);

            // pass 3: Ah * Bl
            uint32_t Bl[8][2];
            #pragma unroll
            for (int p = 0; p < 4; ++p) {
                uint32_t off = (b_row_base + p * 16) * ROWB + ks * 32 + b_kb;
                ldsm_x4(Bl[2*p][0], Bl[2*p][1], Bl[2*p+1][0], Bl[2*p+1][1], stg + OFF_BL + off);
            }
            #pragma unroll
            for (int mi = 0; mi < 2; ++mi)
                #pragma unroll
                for (int ni = 0; ni < 8; ++ni)
                    mma_bf16(acc[mi][ni], Ah[mi], Bl[ni]);
        }
    }

    // ---- epilogue: add bias, split fp32 -> bf16 hi/lo, store ----
    const size_t m_base = arow0 + warp_m * 32;
    const size_t n_base = brow0 + warp_n * 64;
    const int tm = lane >> 2, tn = (lane & 3) * 2;
    #pragma unroll
    for (int mi = 0; mi < 2; ++mi) {
        #pragma unroll
        for (int ni = 0; ni < 8; ++ni) {
            size_t col = n_base + ni * 8 + tn;
            float b0 = __ldg(bias + col), b1 = __ldg(bias + col + 1);
            size_t r0 = m_base + mi * 16 + tm;
            float v00 = acc[mi][ni][0] + b0, v01 = acc[mi][ni][1] + b1;
            float v10 = acc[mi][ni][2] + b0, v11 = acc[mi][ni][3] + b1;
            uint32_t h, l;
            split2(v00, v01, h, l);
            *(uint32_t*)(vhi_out + r0 * LL + col) = h;
            *(uint32_t*)(vlo_out + r0 * LL + col) = l;
            split2(v10, v11, h, l);
            *(uint32_t*)(vhi_out + (r0 + 8) * LL + col) = h;
            *(uint32_t*)(vlo_out + (r0 + 8) * LL + col) = l;
        }
    }
}

// ---------------- fused Householder chain ----------------
// z row held in registers across all 8 reflections:
//   for j: c = -2 (v_j . z)/(v_j . v_j);  z += c * v_j
__global__ void __launch_bounds__(256) hflow_chain_kernel(
    const __nv_bfloat16* __restrict__ Vhi, const __nv_bfloat16* __restrict__ Vlo,
    const float* __restrict__ zin, float* __restrict__ zout)
{
    __shared__ float red[16];
    __shared__ float s_coef;
    const size_t row = blockIdx.x;
    const int tid = threadIdx.x;

    float z[8];
    {
        const float4* z4 = (const float4*)(zin + row * (size_t)LL);
        float4 a = z4[tid], b = z4[tid + 256];
        z[0]=a.x; z[1]=a.y; z[2]=a.z; z[3]=a.w;
        z[4]=b.x; z[5]=b.y; z[6]=b.z; z[7]=b.w;
    }

    #pragma unroll 1
    for (int j = 0; j < NFLOW; ++j) {
        const size_t base = ((size_t)j * BB + row) * (size_t)LL;
        const uint2* vh4 = (const uint2*)(Vhi + base);
        const uint2* vl4 = (const uint2*)(Vlo + base);

        float v[8];
        #pragma unroll
        for (int h = 0; h < 2; ++h) {
            uint2 hv = vh4[tid + h * 256];
            uint2 lv = vl4[tid + h * 256];
            __nv_bfloat162 h0 = *(__nv_bfloat162*)&hv.x, h1 = *(__nv_bfloat162*)&hv.y;
            __nv_bfloat162 l0 = *(__nv_bfloat162*)&lv.x, l1 = *(__nv_bfloat162*)&lv.y;
            v[h*4+0] = __bfloat162float(h0.x) + __bfloat162float(l0.x);
            v[h*4+1] = __bfloat162float(h0.y) + __bfloat162float(l0.y);
            v[h*4+2] = __bfloat162float(h1.x) + __bfloat162float(l1.x);
            v[h*4+3] = __bfloat162float(h1.y) + __bfloat162float(l1.y);
        }

        float vz = 0.f, vv = 0.f;
        #pragma unroll
        for (int i = 0; i < 8; ++i) { vz += v[i] * z[i]; vv += v[i] * v[i]; }
        #pragma unroll
        for (int o = 16; o; o >>= 1) {
            vz += __shfl_xor_sync(0xFFFFFFFFu, vz, o);
            vv += __shfl_xor_sync(0xFFFFFFFFu, vv, o);
        }
        if ((tid & 31) == 0) { red[tid >> 5] = vz; red[8 + (tid >> 5)] = vv; }
        __syncthreads();
        if (tid == 0) {
            float svz = 0.f, svv = 0.f;
            #pragma unroll
            for (int i = 0; i < 8; ++i) { svz += red[i]; svv += red[8 + i]; }
            s_coef = -2.0f * svz / svv;
        }
        __syncthreads();
        const float c = s_coef;
        #pragma unroll
        for (int i = 0; i < 8; ++i) z[i] += c * v[i];
        __syncthreads();   // protect red[] reuse next j
    }

    {
        float4* zo = (float4*)(zout + row * (size_t)LL);
        float4 a, b;
        a.x=z[0]; a.y=z[1]; a.z=z[2]; a.w=z[3];
        b.x=z[4]; b.y=z[5]; b.z=z[6]; b.w=z[7];
        zo[tid] = a; zo[tid + 256] = b;
    }
}

// ---------------- host ----------------
extern "C" void kernel_launch(void* const* d_in, const int* in_sizes, int n_in,
                              void* d_out, int out_size)
{
    const float* z_in   = (const float*)d_in[0];
    const float* h_last = (const float*)d_in[1];
    const float* W0     = (const float*)d_in[2];
    const float* b0     = (const float*)d_in[3];
    const float* Ws     = (const float*)d_in[4];
    const float* bs     = (const float*)d_in[5];
    float* z_out = (float*)d_out;

    void *pVhi, *pVlo, *pHhi, *pHlo, *pWhi, *pWlo;
    cudaGetSymbolAddress(&pVhi, g_Vhi);
    cudaGetSymbolAddress(&pVlo, g_Vlo);
    cudaGetSymbolAddress(&pHhi, g_Hhi);
    cudaGetSymbolAddress(&pHlo, g_Hlo);
    cudaGetSymbolAddress(&pWhi, g_Whi);
    cudaGetSymbolAddress(&pWlo, g_Wlo);

    static bool attr_set = false;
    if (!attr_set) {
        cudaFuncSetAttribute(gemm_kernel, cudaFuncAttributeMaxDynamicSharedMemorySize, SMEM_TOTAL);
        attr_set = true;
    }

    const size_t mat = (size_t)LL * LL;
    const size_t vmat = (size_t)BB * LL;
    {
        int n4 = (int)(vmat / 4);
        split_kernel<<<(n4 + 255) / 256, 256>>>((const float4*)h_last, (uint2*)pHhi, (uint2*)pHlo, n4);
    }
    {
        int n4 = (int)(mat / 4);
        split_kernel<<<(n4 + 255) / 256, 256>>>((const float4*)W0, (uint2*)pWhi, (uint2*)pWlo, n4);
    }
    {
        int n4 = (int)((NFLOW - 1) * mat / 4);
        split_kernel<<<(n4 + 255) / 256, 256>>>((const float4*)Ws,
            (uint2*)((__nv_bfloat16*)pWhi + mat), (uint2*)((__nv_bfloat16*)pWlo + mat), n4);
    }

    dim3 ggrid(BB / BM, LL / BN);   // (64, 16)
    for (int j = 0; j < NFLOW; ++j) {
        const __nv_bfloat16* Ah = (j == 0) ? (const __nv_bfloat16*)pHhi
                                           : (const __nv_bfloat16*)pVhi + (size_t)(j - 1) * vmat;
        const __nv_bfloat16* Al = (j == 0) ? (const __nv_bfloat16*)pHlo
                                           : (const __nv_bfloat16*)pVlo + (size_t)(j - 1) * vmat;
        const __nv_bfloat16* Bh = (const __nv_bfloat16*)pWhi + (size_t)j * mat;
        const __nv_bfloat16* Bl = (const __nv_bfloat16*)pWlo + (size_t)j * mat;
        const float* bias = (j == 0) ? b0 : (bs + (size_t)(j - 1) * LL);
        gemm_kernel<<<ggrid, 256, SMEM_TOTAL>>>(
            Ah, Al, Bh, Bl, bias,
            (__nv_bfloat16*)pVhi + (size_t)j * vmat,
            (__nv_bfloat16*)pVlo + (size_t)j * vmat);
    }

    hflow_chain_kernel<<<BB, 256>>>(
        (const __nv_bfloat16*)pVhi, (const __nv_bfloat16*)pVlo, z_in, z_out);
}

// round 11
// speedup vs baseline: 1.3655x; 1.1954x over previous
#include <cuda_runtime.h>
#include <cuda_bf16.h>
#include <cstdint>
#include <cstddef>

#define DEVINL __device__ __forceinline__

#define BB 8192
#define LL 2048
#define NFLOW 8

// GEMM tiling: CTA 128x128xBK32, 256 thr, 2 CTAs/SM, 3-stage cp.async pipeline
#define BM 128
#define BN 128
#define BK 32
#define NKI (LL / BK)              // 64 k-chunks
#define NSTAGE 3

// swizzled smem: rows of 64B (32 bf16), 16B unit permuted by c16 ^ ((row>>1)&3)
#define SROW 64
#define MAT_BYTES (128 * SROW)              // 8192
#define OFF_AH 0
#define OFF_AL (1 * MAT_BYTES)
#define OFF_BH (2 * MAT_BYTES)
#define OFF_BL (3 * MAT_BYTES)
#define STAGE_BYTES (4 * MAT_BYTES)         // 32768
#define SMEM_TOTAL (NSTAGE * STAGE_BYTES)   // 98304

DEVINL uint32_t sw_off(uint32_t row, uint32_t c16) {
    return row * SROW + ((c16 ^ ((row >> 1) & 3)) << 4);
}

// ---------------- scratch ----------------
__device__ __nv_bfloat16 g_Vhi[(size_t)NFLOW * BB * LL];
__device__ __nv_bfloat16 g_Vlo[(size_t)NFLOW * BB * LL];
__device__ __nv_bfloat16 g_Hhi[(size_t)BB * LL];
__device__ __nv_bfloat16 g_Hlo[(size_t)BB * LL];
__device__ __nv_bfloat16 g_Whi[(size_t)NFLOW * LL * LL];
__device__ __nv_bfloat16 g_Wlo[(size_t)NFLOW * LL * LL];

// ---------------- PTX helpers ----------------
DEVINL uint32_t smem_u32(const void* p) {
    uint32_t a;
    asm("{ .reg .u64 t; cvta.to.shared.u64 t, %1; cvt.u32.u64 %0, t; }" : "=r"(a) : "l"(p));
    return a;
}
DEVINL void cp_async16(uint32_t saddr, const void* gaddr) {
    asm volatile("cp.async.cg.shared.global [%0], [%1], 16;" :: "r"(saddr), "l"(gaddr) : "memory");
}
DEVINL void cp_commit() { asm volatile("cp.async.commit_group;" ::: "memory"); }
DEVINL void cp_wait1() { asm volatile("cp.async.wait_group 1;" ::: "memory"); }
DEVINL void cp_wait0() { asm volatile("cp.async.wait_group 0;" ::: "memory"); }

DEVINL void ldsm_x4(uint32_t& r0, uint32_t& r1, uint32_t& r2, uint32_t& r3, uint32_t saddr) {
    asm volatile("ldmatrix.sync.aligned.m8n8.x4.shared.b16 {%0,%1,%2,%3}, [%4];"
                 : "=r"(r0), "=r"(r1), "=r"(r2), "=r"(r3) : "r"(saddr));
}
DEVINL void mma_bf16(float* d, const uint32_t* a, const uint32_t* b) {
    asm volatile(
        "mma.sync.aligned.m16n8k16.row.col.f32.bf16.bf16.f32 "
        "{%0,%1,%2,%3}, {%4,%5,%6,%7}, {%8,%9}, {%0,%1,%2,%3};"
        : "+f"(d[0]), "+f"(d[1]), "+f"(d[2]), "+f"(d[3])
        : "r"(a[0]), "r"(a[1]), "r"(a[2]), "r"(a[3]), "r"(b[0]), "r"(b[1]));
}
DEVINL uint32_t pack_bf2(float a, float b) {
    __nv_bfloat162 t; t.x = __float2bfloat16(a); t.y = __float2bfloat16(b);
    return *reinterpret_cast<uint32_t*>(&t);
}
DEVINL void split2(float a, float b, uint32_t& hi, uint32_t& lo) {
    float ha = __bfloat162float(__float2bfloat16(a));
    float hb = __bfloat162float(__float2bfloat16(b));
    hi = pack_bf2(ha, hb);
    lo = pack_bf2(a - ha, b - hb);
}

// ---------------- split: fp32 -> bf16 hi/lo ----------------
__global__ void __launch_bounds__(256) split_kernel(
    const float4* __restrict__ src, uint2* __restrict__ hi, uint2* __restrict__ lo, int n4)
{
    int i = blockIdx.x * 256 + threadIdx.x;
    if (i >= n4) return;
    float4 v = src[i];
    uint2 h, l;
    split2(v.x, v.y, h.x, l.x);
    split2(v.z, v.w, h.y, l.y);
    hi[i] = h; lo[i] = l;
}

// ---------------- fill one pipeline stage (chunk at k-offset kb) ----------------
DEVINL void fill_stage(uint32_t stg,
                       const __nv_bfloat16* __restrict__ Ahi, const __nv_bfloat16* __restrict__ Alo,
                       const __nv_bfloat16* __restrict__ Bhi, const __nv_bfloat16* __restrict__ Blo,
                       size_t arow0, size_t brow0, size_t kb, int tid)
{
    // 128 rows x 4 c16-units per matrix = 512 units; 256 threads -> 2 units each
    #pragma unroll
    for (int it = 0; it < 2; ++it) {
        int i = tid + it * 256;
        uint32_t r = (uint32_t)(i >> 2), c = (uint32_t)(i & 3);
        uint32_t so = sw_off(r, c);
        size_t ga = (arow0 + r) * (size_t)LL + kb + c * 8;
        size_t gb = (brow0 + r) * (size_t)LL + kb + c * 8;
        cp_async16(stg + OFF_AH + so, Ahi + ga);
        cp_async16(stg + OFF_AL + so, Alo + ga);
        cp_async16(stg + OFF_BH + so, Bhi + gb);
        cp_async16(stg + OFF_BL + so, Blo + gb);
    }
    cp_commit();
}

// ---------------- GEMM: v' = A @ W^T + bias, epilogue-split into vhi/vlo ----------------
// bf16 3-product: D = Ah*Bh + Al*Bh + Ah*Bl   (fp32 accumulate)
__global__ void __launch_bounds__(256, 2) gemm_kernel(
    const __nv_bfloat16* __restrict__ Ahi, const __nv_bfloat16* __restrict__ Alo,
    const __nv_bfloat16* __restrict__ Bhi, const __nv_bfloat16* __restrict__ Blo,
    const float* __restrict__ bias,
    __nv_bfloat16* __restrict__ vhi_out, __nv_bfloat16* __restrict__ vlo_out)
{
    extern __shared__ char smem[];
    const uint32_t sb = smem_u32(smem);
    const int tid = threadIdx.x;
    const int lane = tid & 31;
    const int wid = tid >> 5;
    const int warp_m = wid & 3;          // 4 warps along M (32 rows)
    const int warp_n = wid >> 2;         // 2 warps along N (64 cols)
    const size_t arow0 = (size_t)blockIdx.x * BM;
    const size_t brow0 = (size_t)blockIdx.y * BN;

    float acc[2][8][4];
    #pragma unroll
    for (int mi = 0; mi < 2; ++mi)
        #pragma unroll
        for (int ni = 0; ni < 8; ++ni)
            #pragma unroll
            for (int q = 0; q < 4; ++q) acc[mi][ni][q] = 0.0f;

    // ldmatrix lane coords (rows within tile, 16B-column units)
    const uint32_t a_rl = (uint32_t)(warp_m * 32 + (lane & 15));   // + s*16
    const uint32_t a_c16 = (uint32_t)(lane >> 4);                  // + ks*2
    const uint32_t b_rl = (uint32_t)(warp_n * 64 + ((lane >> 4) & 1) * 8 + (lane & 7));  // + p*16
    const uint32_t b_c16 = (uint32_t)((lane >> 3) & 1);            // + ks*2

    // ---- prologue: chunks 0,1 into stages 0,1 ----
    fill_stage(sb,               Ahi, Alo, Bhi, Blo, arow0, brow0, 0,  tid);
    fill_stage(sb + STAGE_BYTES, Ahi, Alo, Bhi, Blo, arow0, brow0, BK, tid);

    uint32_t stg = sb;                      // stage holding chunk kc
    uint32_t stg_w = sb + 2 * STAGE_BYTES;  // stage to fill with chunk kc+2

    for (int kc = 0; kc < NKI; ++kc) {
        cp_wait1();          // group kc complete (issued 2 chunks ago)
        __syncthreads();     // chunk kc visible; reads of stage holding kc-1 finished

        if (kc + 2 < NKI)
            fill_stage(stg_w, Ahi, Alo, Bhi, Blo, arow0, brow0, (size_t)(kc + 2) * BK, tid);
        else
            cp_commit();     // keep group arithmetic aligned for wait_group 1

        #pragma unroll
        for (int ks = 0; ks < 2; ++ks) {
            // pass 1: Ah * Bh
            uint32_t Ah[2][4];
            #pragma unroll
            for (int s = 0; s < 2; ++s) {
                uint32_t off = sw_off(a_rl + s * 16, a_c16 + ks * 2);
                ldsm_x4(Ah[s][0], Ah[s][1], Ah[s][2], Ah[s][3], stg + OFF_AH + off);
            }
            uint32_t Bh[8][2];
            #pragma unroll
            for (int p = 0; p < 4; ++p) {
                uint32_t off = sw_off(b_rl + p * 16, b_c16 + ks * 2);
                ldsm_x4(Bh[2*p][0], Bh[2*p][1], Bh[2*p+1][0], Bh[2*p+1][1], stg + OFF_BH + off);
            }
            #pragma unroll
            for (int mi = 0; mi < 2; ++mi)
                #pragma unroll
                for (int ni = 0; ni < 8; ++ni)
                    mma_bf16(acc[mi][ni], Ah[mi], Bh[ni]);

            // pass 2: Al * Bh
            uint32_t Al[2][4];
            #pragma unroll
            for (int s = 0; s < 2; ++s) {
                uint32_t off = sw_off(a_rl + s * 16, a_c16 + ks * 2);
                ldsm_x4(Al[s][0], Al[s][1], Al[s][2], Al[s][3], stg + OFF_AL + off);
            }
            #pragma unroll
            for (int mi = 0; mi < 2; ++mi)
                #pragma unroll
                for (int ni = 0; ni < 8; ++ni)
                    mma_bf16(acc[mi][ni], Al[mi], Bh[ni]);

            // pass 3: Ah * Bl
            uint32_t Bl[8][2];
            #pragma unroll
            for (int p = 0; p < 4; ++p) {
                uint32_t off = sw_off(b_rl + p * 16, b_c16 + ks * 2);
                ldsm_x4(Bl[2*p][0], Bl[2*p][1], Bl[2*p+1][0], Bl[2*p+1][1], stg + OFF_BL + off);
            }
            #pragma unroll
            for (int mi = 0; mi < 2; ++mi)
                #pragma unroll
                for (int ni = 0; ni < 8; ++ni)
                    mma_bf16(acc[mi][ni], Ah[mi], Bl[ni]);
        }

        // rotate stages
        stg_w = stg;
        stg = (stg == sb + 2 * STAGE_BYTES) ? sb : stg + STAGE_BYTES;
    }
    cp_wait0();

    // ---- epilogue: add bias, split fp32 -> bf16 hi/lo, store ----
    const size_t m_base = arow0 + warp_m * 32;
    const size_t n_base = brow0 + warp_n * 64;
    const int tm = lane >> 2, tn = (lane & 3) * 2;
    #pragma unroll
    for (int mi = 0; mi < 2; ++mi) {
        #pragma unroll
        for (int ni = 0; ni < 8; ++ni) {
            size_t col = n_base + ni * 8 + tn;
            float b0 = __ldg(bias + col), b1 = __ldg(bias + col + 1);
            size_t r0 = m_base + mi * 16 + tm;
            float v00 = acc[mi][ni][0] + b0, v01 = acc[mi][ni][1] + b1;
            float v10 = acc[mi][ni][2] + b0, v11 = acc[mi][ni][3] + b1;
            uint32_t h, l;
            split2(v00, v01, h, l);
            *(uint32_t*)(vhi_out + r0 * LL + col) = h;
            *(uint32_t*)(vlo_out + r0 * LL + col) = l;
            split2(v10, v11, h, l);
            *(uint32_t*)(vhi_out + (r0 + 8) * LL + col) = h;
            *(uint32_t*)(vlo_out + (r0 + 8) * LL + col) = l;
        }
    }
}

// ---------------- fused Householder chain ----------------
__global__ void __launch_bounds__(256) hflow_chain_kernel(
    const __nv_bfloat16* __restrict__ Vhi, const __nv_bfloat16* __restrict__ Vlo,
    const float* __restrict__ zin, float* __restrict__ zout)
{
    __shared__ float red[16];
    __shared__ float s_coef;
    const size_t row = blockIdx.x;
    const int tid = threadIdx.x;

    float z[8];
    {
        const float4* z4 = (const float4*)(zin + row * (size_t)LL);
        float4 a = z4[tid], b = z4[tid + 256];
        z[0]=a.x; z[1]=a.y; z[2]=a.z; z[3]=a.w;
        z[4]=b.x; z[5]=b.y; z[6]=b.z; z[7]=b.w;
    }

    #pragma unroll 1
    for (int j = 0; j < NFLOW; ++j) {
        const size_t base = ((size_t)j * BB + row) * (size_t)LL;
        const uint2* vh4 = (const uint2*)(Vhi + base);
        const uint2* vl4 = (const uint2*)(Vlo + base);

        float v[8];
        #pragma unroll
        for (int h = 0; h < 2; ++h) {
            uint2 hv = vh4[tid + h * 256];
            uint2 lv = vl4[tid + h * 256];
            __nv_bfloat162 h0 = *(__nv_bfloat162*)&hv.x, h1 = *(__nv_bfloat162*)&hv.y;
            __nv_bfloat162 l0 = *(__nv_bfloat162*)&lv.x, l1 = *(__nv_bfloat162*)&lv.y;
            v[h*4+0] = __bfloat162float(h0.x) + __bfloat162float(l0.x);
            v[h*4+1] = __bfloat162float(h0.y) + __bfloat162float(l0.y);
            v[h*4+2] = __bfloat162float(h1.x) + __bfloat162float(l1.x);
            v[h*4+3] = __bfloat162float(h1.y) + __bfloat162float(l1.y);
        }

        float vz = 0.f, vv = 0.f;
        #pragma unroll
        for (int i = 0; i < 8; ++i) { vz += v[i] * z[i]; vv += v[i] * v[i]; }
        #pragma unroll
        for (int o = 16; o; o >>= 1) {
            vz += __shfl_xor_sync(0xFFFFFFFFu, vz, o);
            vv += __shfl_xor_sync(0xFFFFFFFFu, vv, o);
        }
        if ((tid & 31) == 0) { red[tid >> 5] = vz; red[8 + (tid >> 5)] = vv; }
        __syncthreads();
        if (tid == 0) {
            float svz = 0.f, svv = 0.f;
            #pragma unroll
            for (int i = 0; i < 8; ++i) { svz += red[i]; svv += red[8 + i]; }
            s_coef = -2.0f * svz / svv;
        }
        __syncthreads();
        const float c = s_coef;
        #pragma unroll
        for (int i = 0; i < 8; ++i) z[i] += c * v[i];
        __syncthreads();
    }

    {
        float4* zo = (float4*)(zout + row * (size_t)LL);
        float4 a, b;
        a.x=z[0]; a.y=z[1]; a.z=z[2]; a.w=z[3];
        b.x=z[4]; b.y=z[5]; b.z=z[6]; b.w=z[7];
        zo[tid] = a; zo[tid + 256] = b;
    }
}

// ---------------- host ----------------
extern "C" void kernel_launch(void* const* d_in, const int* in_sizes, int n_in,
                              void* d_out, int out_size)
{
    const float* z_in   = (const float*)d_in[0];
    const float* h_last = (const float*)d_in[1];
    const float* W0     = (const float*)d_in[2];
    const float* b0     = (const float*)d_in[3];
    const float* Ws     = (const float*)d_in[4];
    const float* bs     = (const float*)d_in[5];
    float* z_out = (float*)d_out;

    void *pVhi, *pVlo, *pHhi, *pHlo, *pWhi, *pWlo;
    cudaGetSymbolAddress(&pVhi, g_Vhi);
    cudaGetSymbolAddress(&pVlo, g_Vlo);
    cudaGetSymbolAddress(&pHhi, g_Hhi);
    cudaGetSymbolAddress(&pHlo, g_Hlo);
    cudaGetSymbolAddress(&pWhi, g_Whi);
    cudaGetSymbolAddress(&pWlo, g_Wlo);

    static bool attr_set = false;
    if (!attr_set) {
        cudaFuncSetAttribute(gemm_kernel, cudaFuncAttributeMaxDynamicSharedMemorySize, SMEM_TOTAL);
        attr_set = true;
    }

    const size_t mat = (size_t)LL * LL;
    const size_t vmat = (size_t)BB * LL;
    {
        int n4 = (int)(vmat / 4);
        split_kernel<<<(n4 + 255) / 256, 256>>>((const float4*)h_last, (uint2*)pHhi, (uint2*)pHlo, n4);
    }
    {
        int n4 = (int)(mat / 4);
        split_kernel<<<(n4 + 255) / 256, 256>>>((const float4*)W0, (uint2*)pWhi, (uint2*)pWlo, n4);
    }
    {
        int n4 = (int)((NFLOW - 1) * mat / 4);
        split_kernel<<<(n4 + 255) / 256, 256>>>((const float4*)Ws,
            (uint2*)((__nv_bfloat16*)pWhi + mat), (uint2*)((__nv_bfloat16*)pWlo + mat), n4);
    }

    dim3 ggrid(BB / BM, LL / BN);   // (64, 16)
    for (int j = 0; j < NFLOW; ++j) {
        const __nv_bfloat16* Ah = (j == 0) ? (const __nv_bfloat16*)pHhi
                                           : (const __nv_bfloat16*)pVhi + (size_t)(j - 1) * vmat;
        const __nv_bfloat16* Al = (j == 0) ? (const __nv_bfloat16*)pHlo
                                           : (const __nv_bfloat16*)pVlo + (size_t)(j - 1) * vmat;
        const __nv_bfloat16* Bh = (const __nv_bfloat16*)pWhi + (size_t)j * mat;
        const __nv_bfloat16* Bl = (const __nv_bfloat16*)pWlo + (size_t)j * mat;
        const float* bias = (j == 0) ? b0 : (bs + (size_t)(j - 1) * LL);
        gemm_kernel<<<ggrid, 256, SMEM_TOTAL>>>(
            Ah, Al, Bh, Bl, bias,
            (__nv_bfloat16*)pVhi + (size_t)j * vmat,
            (__nv_bfloat16*)pVlo + (size_t)j * vmat);
    }

    hflow_chain_kernel<<<BB, 256>>>(
        (const __nv_bfloat16*)pVhi, (const __nv_bfloat16*)pVlo, z_in, z_out);
}

// round 12
// speedup vs baseline: 1.3656x; 1.0001x over previous
#include <cuda_runtime.h>
#include <cuda_bf16.h>
#include <cstdint>
#include <cstddef>

#define DEVINL __device__ __forceinline__

#define BB 8192
#define LL 2048
#define NFLOW 8

// GEMM tiling: CTA 128x128xBK32, 256 thr, 2 CTAs/SM, 3-stage cp.async pipeline
#define BM 128
#define BN 128
#define BK 32
#define NKI (LL / BK)              // 64 k-chunks
#define NSTAGE 3

// swizzled smem: rows of 64B (32 bf16), 16B unit permuted by c16 ^ ((row>>1)&3)
#define SROW 64
#define MAT_BYTES (128 * SROW)              // 8192
#define OFF_AH 0
#define OFF_AL (1 * MAT_BYTES)
#define OFF_BH (2 * MAT_BYTES)
#define OFF_BL (3 * MAT_BYTES)
#define STAGE_BYTES (4 * MAT_BYTES)         // 32768
#define SMEM_TOTAL (NSTAGE * STAGE_BYTES)   // 98304

DEVINL uint32_t sw_off(uint32_t row, uint32_t c16) {
    return row * SROW + ((c16 ^ ((row >> 1) & 3)) << 4);
}

// ---------------- scratch ----------------
__device__ __nv_bfloat16 g_Vhi[(size_t)NFLOW * BB * LL];
__device__ __nv_bfloat16 g_Vlo[(size_t)NFLOW * BB * LL];
__device__ __nv_bfloat16 g_Hhi[(size_t)BB * LL];
__device__ __nv_bfloat16 g_Hlo[(size_t)BB * LL];
__device__ __nv_bfloat16 g_Whi[(size_t)NFLOW * LL * LL];
__device__ __nv_bfloat16 g_Wlo[(size_t)NFLOW * LL * LL];

// ---------------- PTX helpers ----------------
DEVINL uint32_t smem_u32(const void* p) {
    uint32_t a;
    asm("{ .reg .u64 t; cvta.to.shared.u64 t, %1; cvt.u32.u64 %0, t; }" : "=r"(a) : "l"(p));
    return a;
}
DEVINL void cp_async16(uint32_t saddr, const void* gaddr) {
    asm volatile("cp.async.cg.shared.global [%0], [%1], 16;" :: "r"(saddr), "l"(gaddr) : "memory");
}
DEVINL void cp_commit() { asm volatile("cp.async.commit_group;" ::: "memory"); }
DEVINL void cp_wait1() { asm volatile("cp.async.wait_group 1;" ::: "memory"); }
DEVINL void cp_wait0() { asm volatile("cp.async.wait_group 0;" ::: "memory"); }

DEVINL void ldsm_x4(uint32_t& r0, uint32_t& r1, uint32_t& r2, uint32_t& r3, uint32_t saddr) {
    asm volatile("ldmatrix.sync.aligned.m8n8.x4.shared.b16 {%0,%1,%2,%3}, [%4];"
                 : "=r"(r0), "=r"(r1), "=r"(r2), "=r"(r3) : "r"(saddr));
}
DEVINL void mma_bf16(float* d, const uint32_t* a, const uint32_t* b) {
    asm volatile(
        "mma.sync.aligned.m16n8k16.row.col.f32.bf16.bf16.f32 "
        "{%0,%1,%2,%3}, {%4,%5,%6,%7}, {%8,%9}, {%0,%1,%2,%3};"
        : "+f"(d[0]), "+f"(d[1]), "+f"(d[2]), "+f"(d[3])
        : "r"(a[0]), "r"(a[1]), "r"(a[2]), "r"(a[3]), "r"(b[0]), "r"(b[1]));
}
DEVINL uint32_t pack_bf2(float a, float b) {
    __nv_bfloat162 t; t.x = __float2bfloat16(a); t.y = __float2bfloat16(b);
    return *reinterpret_cast<uint32_t*>(&t);
}
DEVINL void split2(float a, float b, uint32_t& hi, uint32_t& lo) {
    float ha = __bfloat162float(__float2bfloat16(a));
    float hb = __bfloat162float(__float2bfloat16(b));
    hi = pack_bf2(ha, hb);
    lo = pack_bf2(a - ha, b - hb);
}

// ---------------- split: fp32 -> bf16 hi/lo ----------------
__global__ void __launch_bounds__(256) split_kernel(
    const float4* __restrict__ src, uint2* __restrict__ hi, uint2* __restrict__ lo, int n4)
{
    int i = blockIdx.x * 256 + threadIdx.x;
    if (i >= n4) return;
    float4 v = src[i];
    uint2 h, l;
    split2(v.x, v.y, h.x, l.x);
    split2(v.z, v.w, h.y, l.y);
    hi[i] = h; lo[i] = l;
}

// ---------------- fill one pipeline stage (chunk at k-offset kb) ----------------
DEVINL void fill_stage(uint32_t stg,
                       const __nv_bfloat16* __restrict__ Ahi, const __nv_bfloat16* __restrict__ Alo,
                       const __nv_bfloat16* __restrict__ Bhi, const __nv_bfloat16* __restrict__ Blo,
                       size_t arow0, size_t brow0, size_t kb, int tid)
{
    #pragma unroll
    for (int it = 0; it < 2; ++it) {
        int i = tid + it * 256;
        uint32_t r = (uint32_t)(i >> 2), c = (uint32_t)(i & 3);
        uint32_t so = sw_off(r, c);
        size_t ga = (arow0 + r) * (size_t)LL + kb + c * 8;
        size_t gb = (brow0 + r) * (size_t)LL + kb + c * 8;
        cp_async16(stg + OFF_AH + so, Ahi + ga);
        cp_async16(stg + OFF_AL + so, Alo + ga);
        cp_async16(stg + OFF_BH + so, Bhi + gb);
        cp_async16(stg + OFF_BL + so, Blo + gb);
    }
    cp_commit();
}

// ---------------- GEMM: v' = A @ W^T + bias, epilogue-split into vhi/vlo ----------------
// bf16 3-product: D = Ah*Bh + Al*Bh + Ah*Bl   (fp32 accumulate)
// Fragment loads are manually interleaved into the mma streams (volatile asm
// preserves order; other warps cover the remaining exposed latency).
__global__ void __launch_bounds__(256, 2) gemm_kernel(
    const __nv_bfloat16* __restrict__ Ahi, const __nv_bfloat16* __restrict__ Alo,
    const __nv_bfloat16* __restrict__ Bhi, const __nv_bfloat16* __restrict__ Blo,
    const float* __restrict__ bias,
    __nv_bfloat16* __restrict__ vhi_out, __nv_bfloat16* __restrict__ vlo_out)
{
    extern __shared__ char smem[];
    const uint32_t sb = smem_u32(smem);
    const int tid = threadIdx.x;
    const int lane = tid & 31;
    const int wid = tid >> 5;
    const int warp_m = wid & 3;          // 4 warps along M (32 rows)
    const int warp_n = wid >> 2;         // 2 warps along N (64 cols)
    const size_t arow0 = (size_t)blockIdx.x * BM;
    const size_t brow0 = (size_t)blockIdx.y * BN;

    float acc[2][8][4];
    #pragma unroll
    for (int mi = 0; mi < 2; ++mi)
        #pragma unroll
        for (int ni = 0; ni < 8; ++ni)
            #pragma unroll
            for (int q = 0; q < 4; ++q) acc[mi][ni][q] = 0.0f;

    // ldmatrix lane coords
    const uint32_t a_rl = (uint32_t)(warp_m * 32 + (lane & 15));
    const uint32_t a_c16 = (uint32_t)(lane >> 4);
    const uint32_t b_rl = (uint32_t)(warp_n * 64 + ((lane >> 4) & 1) * 8 + (lane & 7));
    const uint32_t b_c16 = (uint32_t)((lane >> 3) & 1);

    // ---- prologue: chunks 0,1 into stages 0,1 ----
    fill_stage(sb,               Ahi, Alo, Bhi, Blo, arow0, brow0, 0,  tid);
    fill_stage(sb + STAGE_BYTES, Ahi, Alo, Bhi, Blo, arow0, brow0, BK, tid);

    uint32_t stg = sb;
    uint32_t stg_w = sb + 2 * STAGE_BYTES;

    for (int kc = 0; kc < NKI; ++kc) {
        cp_wait1();
        __syncthreads();

        if (kc + 2 < NKI)
            fill_stage(stg_w, Ahi, Alo, Bhi, Blo, arow0, brow0, (size_t)(kc + 2) * BK, tid);
        else
            cp_commit();

        #pragma unroll
        for (int ks = 0; ks < 2; ++ks) {
            uint32_t Ah[2][4], Bh[8][2], Al[2][4], Bl[8][2];
            const uint32_t offA0 = sw_off(a_rl,      a_c16 + ks * 2);
            const uint32_t offA1 = sw_off(a_rl + 16, a_c16 + ks * 2);
            uint32_t offB[4];
            #pragma unroll
            for (int p = 0; p < 4; ++p) offB[p] = sw_off(b_rl + p * 16, b_c16 + ks * 2);

            // header loads for pass 1
            ldsm_x4(Ah[0][0], Ah[0][1], Ah[0][2], Ah[0][3], stg + OFF_AH + offA0);
            ldsm_x4(Ah[1][0], Ah[1][1], Ah[1][2], Ah[1][3], stg + OFF_AH + offA1);
            #pragma unroll
            for (int p = 0; p < 4; ++p)
                ldsm_x4(Bh[2*p][0], Bh[2*p][1], Bh[2*p+1][0], Bh[2*p+1][1], stg + OFF_BH + offB[p]);

            // ---- pass 1: Ah * Bh, with Al loads interleaved ----
            mma_bf16(acc[0][0], Ah[0], Bh[0]);
            mma_bf16(acc[0][1], Ah[0], Bh[1]);
            mma_bf16(acc[0][2], Ah[0], Bh[2]);
            mma_bf16(acc[0][3], Ah[0], Bh[3]);
            ldsm_x4(Al[0][0], Al[0][1], Al[0][2], Al[0][3], stg + OFF_AL + offA0);
            mma_bf16(acc[0][4], Ah[0], Bh[4]);
            mma_bf16(acc[0][5], Ah[0], Bh[5]);
            mma_bf16(acc[0][6], Ah[0], Bh[6]);
            mma_bf16(acc[0][7], Ah[0], Bh[7]);
            ldsm_x4(Al[1][0], Al[1][1], Al[1][2], Al[1][3], stg + OFF_AL + offA1);
            #pragma unroll
            for (int ni = 0; ni < 8; ++ni)
                mma_bf16(acc[1][ni], Ah[1], Bh[ni]);

            // ---- pass 2: Al * Bh, with Bl loads interleaved ----
            mma_bf16(acc[0][0], Al[0], Bh[0]);
            mma_bf16(acc[0][1], Al[0], Bh[1]);
            ldsm_x4(Bl[0][0], Bl[0][1], Bl[1][0], Bl[1][1], stg + OFF_BL + offB[0]);
            mma_bf16(acc[0][2], Al[0], Bh[2]);
            mma_bf16(acc[0][3], Al[0], Bh[3]);
            ldsm_x4(Bl[2][0], Bl[2][1], Bl[3][0], Bl[3][1], stg + OFF_BL + offB[1]);
            mma_bf16(acc[0][4], Al[0], Bh[4]);
            mma_bf16(acc[0][5], Al[0], Bh[5]);
            ldsm_x4(Bl[4][0], Bl[4][1], Bl[5][0], Bl[5][1], stg + OFF_BL + offB[2]);
            mma_bf16(acc[0][6], Al[0], Bh[6]);
            mma_bf16(acc[0][7], Al[0], Bh[7]);
            ldsm_x4(Bl[6][0], Bl[6][1], Bl[7][0], Bl[7][1], stg + OFF_BL + offB[3]);
            #pragma unroll
            for (int ni = 0; ni < 8; ++ni)
                mma_bf16(acc[1][ni], Al[1], Bh[ni]);

            // ---- pass 3: Ah * Bl ----
            #pragma unroll
            for (int mi = 0; mi < 2; ++mi)
                #pragma unroll
                for (int ni = 0; ni < 8; ++ni)
                    mma_bf16(acc[mi][ni], Ah[mi], Bl[ni]);
        }

        stg_w = stg;
        stg = (stg == sb + 2 * STAGE_BYTES) ? sb : stg + STAGE_BYTES;
    }
    cp_wait0();

    // ---- epilogue: add bias, split fp32 -> bf16 hi/lo, store ----
    const size_t m_base = arow0 + warp_m * 32;
    const size_t n_base = brow0 + warp_n * 64;
    const int tm = lane >> 2, tn = (lane & 3) * 2;
    #pragma unroll
    for (int mi = 0; mi < 2; ++mi) {
        #pragma unroll
        for (int ni = 0; ni < 8; ++ni) {
            size_t col = n_base + ni * 8 + tn;
            float b0 = __ldg(bias + col), b1 = __ldg(bias + col + 1);
            size_t r0 = m_base + mi * 16 + tm;
            float v00 = acc[mi][ni][0] + b0, v01 = acc[mi][ni][1] + b1;
            float v10 = acc[mi][ni][2] + b0, v11 = acc[mi][ni][3] + b1;
            uint32_t h, l;
            split2(v00, v01, h, l);
            *(uint32_t*)(vhi_out + r0 * LL + col) = h;
            *(uint32_t*)(vlo_out + r0 * LL + col) = l;
            split2(v10, v11, h, l);
            *(uint32_t*)(vhi_out + (r0 + 8) * LL + col) = h;
            *(uint32_t*)(vlo_out + (r0 + 8) * LL + col) = l;
        }
    }
}

// ---------------- fused Householder chain ----------------
__global__ void __launch_bounds__(256) hflow_chain_kernel(
    const __nv_bfloat16* __restrict__ Vhi, const __nv_bfloat16* __restrict__ Vlo,
    const float* __restrict__ zin, float* __restrict__ zout)
{
    __shared__ float red[16];
    __shared__ float s_coef;
    const size_t row = blockIdx.x;
    const int tid = threadIdx.x;

    float z[8];
    {
        const float4* z4 = (const float4*)(zin + row * (size_t)LL);
        float4 a = z4[tid], b = z4[tid + 256];
        z[0]=a.x; z[1]=a.y; z[2]=a.z; z[3]=a.w;
        z[4]=b.x; z[5]=b.y; z[6]=b.z; z[7]=b.w;
    }

    #pragma unroll 1
    for (int j = 0; j < NFLOW; ++j) {
        const size_t base = ((size_t)j * BB + row) * (size_t)LL;
        const uint2* vh4 = (const uint2*)(Vhi + base);
        const uint2* vl4 = (const uint2*)(Vlo + base);

        float v[8];
        #pragma unroll
        for (int h = 0; h < 2; ++h) {
            uint2 hv = vh4[tid + h * 256];
            uint2 lv = vl4[tid + h * 256];
            __nv_bfloat162 h0 = *(__nv_bfloat162*)&hv.x, h1 = *(__nv_bfloat162*)&hv.y;
            __nv_bfloat162 l0 = *(__nv_bfloat162*)&lv.x, l1 = *(__nv_bfloat162*)&lv.y;
            v[h*4+0] = __bfloat162float(h0.x) + __bfloat162float(l0.x);
            v[h*4+1] = __bfloat162float(h0.y) + __bfloat162float(l0.y);
            v[h*4+2] = __bfloat162float(h1.x) + __bfloat162float(l1.x);
            v[h*4+3] = __bfloat162float(h1.y) + __bfloat162float(l1.y);
        }

        float vz = 0.f, vv = 0.f;
        #pragma unroll
        for (int i = 0; i < 8; ++i) { vz += v[i] * z[i]; vv += v[i] * v[i]; }
        #pragma unroll
        for (int o = 16; o; o >>= 1) {
            vz += __shfl_xor_sync(0xFFFFFFFFu, vz, o);
            vv += __shfl_xor_sync(0xFFFFFFFFu, vv, o);
        }
        if ((tid & 31) == 0) { red[tid >> 5] = vz; red[8 + (tid >> 5)] = vv; }
        __syncthreads();
        if (tid == 0) {
            float svz = 0.f, svv = 0.f;
            #pragma unroll
            for (int i = 0; i < 8; ++i) { svz += red[i]; svv += red[8 + i]; }
            s_coef = -2.0f * svz / svv;
        }
        __syncthreads();
        const float c = s_coef;
        #pragma unroll
        for (int i = 0; i < 8; ++i) z[i] += c * v[i];
        __syncthreads();
    }

    {
        float4* zo = (float4*)(zout + row * (size_t)LL);
        float4 a, b;
        a.x=z[0]; a.y=z[1]; a.z=z[2]; a.w=z[3];
        b.x=z[4]; b.y=z[5]; b.z=z[6]; b.w=z[7];
        zo[tid] = a; zo[tid + 256] = b;
    }
}

// ---------------- host ----------------
extern "C" void kernel_launch(void* const* d_in, const int* in_sizes, int n_in,
                              void* d_out, int out_size)
{
    const float* z_in   = (const float*)d_in[0];
    const float* h_last = (const float*)d_in[1];
    const float* W0     = (const float*)d_in[2];
    const float* b0     = (const float*)d_in[3];
    const float* Ws     = (const float*)d_in[4];
    const float* bs     = (const float*)d_in[5];
    float* z_out = (float*)d_out;

    void *pVhi, *pVlo, *pHhi, *pHlo, *pWhi, *pWlo;
    cudaGetSymbolAddress(&pVhi, g_Vhi);
    cudaGetSymbolAddress(&pVlo, g_Vlo);
    cudaGetSymbolAddress(&pHhi, g_Hhi);
    cudaGetSymbolAddress(&pHlo, g_Hlo);
    cudaGetSymbolAddress(&pWhi, g_Whi);
    cudaGetSymbolAddress(&pWlo, g_Wlo);

    static bool attr_set = false;
    if (!attr_set) {
        cudaFuncSetAttribute(gemm_kernel, cudaFuncAttributeMaxDynamicSharedMemorySize, SMEM_TOTAL);
        attr_set = true;
    }

    const size_t mat = (size_t)LL * LL;
    const size_t vmat = (size_t)BB * LL;
    {
        int n4 = (int)(vmat / 4);
        split_kernel<<<(n4 + 255) / 256, 256>>>((const float4*)h_last, (uint2*)pHhi, (uint2*)pHlo, n4);
    }
    {
        int n4 = (int)(mat / 4);
        split_kernel<<<(n4 + 255) / 256, 256>>>((const float4*)W0, (uint2*)pWhi, (uint2*)pWlo, n4);
    }
    {
        int n4 = (int)((NFLOW - 1) * mat / 4);
        split_kernel<<<(n4 + 255) / 256, 256>>>((const float4*)Ws,
            (uint2*)((__nv_bfloat16*)pWhi + mat), (uint2*)((__nv_bfloat16*)pWlo + mat), n4);
    }

    dim3 ggrid(BB / BM, LL / BN);   // (64, 16)
    for (int j = 0; j < NFLOW; ++j) {
        const __nv_bfloat16* Ah = (j == 0) ? (const __nv_bfloat16*)pHhi
                                           : (const __nv_bfloat16*)pVhi + (size_t)(j - 1) * vmat;
        const __nv_bfloat16* Al = (j == 0) ? (const __nv_bfloat16*)pHlo
                                           : (const __nv_bfloat16*)pVlo + (size_t)(j - 1) * vmat;
        const __nv_bfloat16* Bh = (const __nv_bfloat16*)pWhi + (size_t)j * mat;
        const __nv_bfloat16* Bl = (const __nv_bfloat16*)pWlo + (size_t)j * mat;
        const float* bias = (j == 0) ? b0 : (bs + (size_t)(j - 1) * LL);
        gemm_kernel<<<ggrid, 256, SMEM_TOTAL>>>(
            Ah, Al, Bh, Bl, bias,
            (__nv_bfloat16*)pVhi + (size_t)j * vmat,
            (__nv_bfloat16*)pVlo + (size_t)j * vmat);
    }

    hflow_chain_kernel<<<BB, 256>>>(
        (const __nv_bfloat16*)pVhi, (const __nv_bfloat16*)pVlo, z_in, z_out);
}